// round 5
// baseline (speedup 1.0000x reference)
#include <cuda_runtime.h>
#include <cuda_bf16.h>

#define NATOMS 256
#define NMOL   4
#define NPAIRS 8192
#define NK     84                 // half-space k-vectors
#define NBLK_PAIR 128             // 128 blocks x 255 pairs = 32640 = 256*255/2
#define KEC      14.3996f
#define AA       0.3f
#define PI_F     3.14159265358979323846f
#define SQRTPI_F 1.7724538509055160273f
#define TWOPI_F  6.2831853071795864769f
#define INV2A      (1.0f/(2.0f*AA))
#define TWOA_SQPI  (2.0f*AA/SQRTPI_F)
#define FOURA_SQPI (4.0f*AA/SQRTPI_F)
#define INV_A_SQPI (1.0f/(AA*SQRTPI_F))

// global accumulators: zero at load; k_fin re-zeroes after use each call
__device__ float  g_G[NATOMS][3];
__device__ float  g_U[NATOMS][6];
__device__ float  g_T[NATOMS*NMOL][6];
__device__ double g_Ec;
__device__ double g_Eb[NMOL];

__device__ __forceinline__ float blockReduce256(float v, float* sh) {
    const unsigned full = 0xffffffffu;
    #pragma unroll
    for (int o = 16; o > 0; o >>= 1) v += __shfl_down_sync(full, v, o);
    int lane = threadIdx.x & 31, w = threadIdx.x >> 5;
    if (lane == 0) sh[w] = v;
    __syncthreads();
    float r = 0.f;
    if (w == 0) {
        r = (lane < 8) ? sh[lane] : 0.f;
        #pragma unroll
        for (int o = 4; o > 0; o >>= 1) r += __shfl_down_sync(full, r, o);
    }
    __syncthreads();
    return r;
}

// erfc(x)*exp(x*x), x>=0 (A&S 7.1.26)
__device__ __forceinline__ float erfcx_p(float x) {
    float t = __fdividef(1.f, fmaf(0.3275911f, x, 1.0f));
    float p = fmaf(t, 1.061405429f, -1.453152027f);
    p = fmaf(t, p, 1.421413741f);
    p = fmaf(t, p, -0.284496736f);
    p = fmaf(t, p, 0.254829592f);
    return t * p;
}

__global__ void __launch_bounds__(256) k_main(const float* __restrict__ R,
                                              const float* __restrict__ shift,
                                              const float* __restrict__ q,
                                              const float* __restrict__ cell,
                                              const float* __restrict__ recip,
                                              const float* __restrict__ off,
                                              const float* __restrict__ r0_,
                                              const float* __restrict__ n_,
                                              const int* __restrict__ ii,
                                              const int* __restrict__ jj,
                                              const int* __restrict__ idxm,
                                              const int* __restrict__ isf) {
    __shared__ float  sRx[NATOMS], sRy[NATOMS], sRz[NATOMS], sq[NATOMS];
    __shared__ int    sfm[NATOMS];
    __shared__ float4 skA[NK];   // hx, hy, hz, |h|
    __shared__ float4 skB[NK];   // u, exp(-u^2), 1/|h|, 0
    __shared__ float  sax[25], say[25], saz[25];
    __shared__ float  red[32];

    int t = threadIdx.x;

    // ---- per-block preamble (replaces k_prep) ----
    float c0x = cell[0], c0y = cell[1], c0z = cell[2];
    float c1x = cell[3], c1y = cell[4], c1z = cell[5];
    float K0x = TWOPI_F * recip[0], K0y = TWOPI_F * recip[1], K0z = TWOPI_F * recip[2];
    float K1x = TWOPI_F * recip[3], K1y = TWOPI_F * recip[4], K1z = TWOPI_F * recip[5];
    float crx = c0y * c1z - c0z * c1y;
    float cry = c0z * c1x - c0x * c1z;
    float crz = c0x * c1y - c0y * c1x;
    float area = sqrtf(crx * crx + cry * cry + crz * crz);

    {
        int m = idxm[t];
        float f = (isf[t] > 0) ? 1.f : 0.f;
        sRx[t] = R[t * 3 + 0] + f * shift[m * 3 + 0];
        sRy[t] = R[t * 3 + 1] + f * shift[m * 3 + 1];
        sRz[t] = R[t * 3 + 2] + f * shift[m * 3 + 2];
        sq[t]  = q[t];
        sfm[t] = (isf[t] > 0) ? m : -1;
    }
    if (t < NK) {
        int k0, j1, sg;
        if (t < 6) { k0 = 0; j1 = t + 1; sg = 1; }
        else {
            int u2 = t - 6;
            k0 = 1 + u2 / 13;
            int r = u2 % 13;
            if (r == 0) { j1 = 0; sg = 1; }
            else { j1 = (r + 1) >> 1; sg = (r & 1) ? 1 : -1; }
        }
        float fj = (float)(sg * j1), fk = (float)k0;
        float hx = fk * K0x + fj * K1x;
        float hy = fk * K0y + fj * K1y;
        float hz = fk * K0z + fj * K1z;
        float d2 = hx * hx + hy * hy + hz * hz;
        float dd = sqrtf(d2);
        float uu = dd * INV2A;
        skA[t] = make_float4(hx, hy, hz, dd);
        skB[t] = make_float4(uu, __expf(-uu * uu), __fdividef(1.f, dd), 0.f);
    }
    if (t < 25) {
        float fn0 = (float)(t / 5 - 2), fn1 = (float)(t % 5 - 2);
        sax[t] = fn0 * c0x + fn1 * c1x;
        say[t] = fn0 * c0y + fn1 * c1y;
        saz[t] = fn0 * c0z + fn1 * c1z;
    }
    __syncthreads();

    if (blockIdx.x < NBLK_PAIR) {
        int b = blockIdx.x;
        int i = 0, j = 0;
        bool isPair = (t < 255);
        bool isDiag = (t == 255) && (b == 0);
        {
            int n1 = 255 - b;
            if (t < n1)       { i = b;       j = b + 1 + t; }
            else if (t < 255) { i = 255 - b; j = i + 1 + (t - n1); }
        }

        float E = 0.f;
        if (isPair || isDiag) {
            float dx = 0.f, dy = 0.f, dz = 0.f, qq, wE;
            if (isPair) {
                dx = sRx[i] - sRx[j];
                dy = sRy[i] - sRy[j];
                dz = sRz[i] - sRz[j];
                qq = sq[i] * sq[j];
                wE = 2.f;
            } else {
                float s2 = 0.f;
                #pragma unroll 8
                for (int a2 = 0; a2 < NATOMS; a2++) s2 = fmaf(sq[a2], sq[a2], s2);
                qq = s2;
                wE = 1.f;
            }

            float az = AA * dz, azsq = az * az;
            float gzp = __expf(-azsq);

            float Ek = 0.f, Gkx = 0.f, Gky = 0.f, Gkz = 0.f;
            float Kxx = 0.f, Kyy = 0.f, Kzz = 0.f, Kxy = 0.f, Kxz = 0.f, Kyz = 0.f;

            auto doK = [&](float cT, float sT, int e) {
                float4 A = skA[e];
                float4 B = skB[e];
                float x1 = B.x + az, x2 = B.x - az;
                float gp = B.y * gzp;
                float p1 = gp * erfcx_p(fabsf(x1));
                float p2 = gp * erfcx_p(fabsf(x2));
                float e1 = (x1 >= 0.f) ? p1 : 2.f * __expf(A.w * dz) - p1;
                float e2 = (x2 >= 0.f) ? p2 : 2.f * __expf(-A.w * dz) - p2;
                float s  = e1 + e2;
                float F   = s * B.z;
                float Fz  = e1 - e2;
                float Fzz = fmaf(A.w, s, -FOURA_SQPI * gp);
                float cF  = cT * F;
                float sF  = sT * F;
                float sFz = sT * Fz;
                Ek  += cF;
                Gkx -= sF * A.x;
                Gky -= sF * A.y;
                Gkz += cT * Fz - sF * A.z;
                Kxx -= cF * A.x * A.x;
                Kyy -= cF * A.y * A.y;
                Kxy -= cF * A.x * A.y;
                Kxz -= cF * A.x * A.z + sFz * A.x;
                Kyz -= cF * A.y * A.z + sFz * A.y;
                Kzz += cT * Fzz - cF * A.z * A.z - 2.f * sFz * A.z;
            };

            float alpha = K0x * dx + K0y * dy + K0z * dz;
            float beta  = K1x * dx + K1y * dy + K1z * dz;
            float sa, ca, sb, cb;
            sincosf(alpha, &sa, &ca);
            sincosf(beta,  &sb, &cb);

            int kidx = 0;
            {   // k0 = 0, j1 = 1..6
                float cB = cb, sB = sb;
                #pragma unroll 1
                for (int j1 = 1; j1 <= 6; j1++) {
                    doK(cB, sB, kidx++);
                    float cBn = cB * cb - sB * sb;
                    sB = sB * cb + cB * sb;
                    cB = cBn;
                }
            }
            float cA = ca, sA = sa;
            #pragma unroll 1
            for (int k0 = 1; k0 <= 6; k0++) {
                doK(cA, sA, kidx++);
                float cB = cb, sB = sb;
                #pragma unroll 1
                for (int j1 = 1; j1 <= 6; j1++) {
                    float cP = cA * cB - sA * sB, sP = sA * cB + cA * sB;
                    doK(cP, sP, kidx++);
                    float cM = cA * cB + sA * sB, sM = sA * cB - cA * sB;
                    doK(cM, sM, kidx++);
                    float cBn = cB * cb - sB * sb;
                    sB = sB * cb + cB * sb;
                    cB = cBn;
                }
                float cAn = cA * ca - sA * sa;
                sA = sA * ca + cA * sa;
                cA = cAn;
            }

            // S2 (z-only)
            float erfz = copysignf(1.f - erfcx_p(fabsf(az)) * gzp, az);
            Ek  -= dz * erfz + gzp * INV_A_SQPI;
            Gkz -= erfz;
            Kzz -= TWOA_SQPI * gzp;

            // real-space images
            float Er = 0.f, Grx = 0.f, Gry = 0.f, Grz = 0.f;
            float Rxx = 0.f, Ryy = 0.f, Rzz = 0.f, Rxy = 0.f, Rxz = 0.f, Ryz = 0.f;
            #pragma unroll 1
            for (int im = 0; im < 25; im++) {
                float rx = dx + sax[im];
                float ry = dy + say[im];
                float rz = dz + saz[im];
                float dd2 = rx * rx + ry * ry + rz * rz;
                if (dd2 > 0.f && dd2 < (81.0f / (AA * AA))) {
                    float invd  = rsqrtf(dd2);
                    float dr    = dd2 * invd;
                    float ad    = AA * dr;
                    float e     = __expf(-ad * ad);
                    float tt    = erfcx_p(ad) * e;
                    float invd2 = invd * invd;
                    Er += tt * invd;
                    float up  = -(TWOA_SQPI * e + tt * invd) * invd;
                    float upp = TWOA_SQPI * e * (2.f * AA * AA + 2.f * invd2) + 2.f * tt * invd * invd2;
                    float s1v = up * invd;
                    Grx += s1v * rx; Gry += s1v * ry; Grz += s1v * rz;
                    float w = (upp - s1v) * invd2;
                    Rxx += w * rx * rx + s1v;
                    Ryy += w * ry * ry + s1v;
                    Rzz += w * rz * rz + s1v;
                    Rxy += w * rx * ry;
                    Rxz += w * rx * rz;
                    Ryz += w * ry * rz;
                }
            }

            float pk = qq * (KEC * PI_F / area);
            float p3 = qq * (0.5f * KEC);
            E = wE * (pk * Ek + p3 * Er);

            if (isPair) {
                float Gx = 8.f * (pk * Gkx + p3 * Grx);
                float Gy = 8.f * (pk * Gky + p3 * Gry);
                float Gz = 8.f * (pk * Gkz + p3 * Grz);
                atomicAdd(&g_G[i][0],  Gx);
                atomicAdd(&g_G[i][1],  Gy);
                atomicAdd(&g_G[i][2],  Gz);
                atomicAdd(&g_G[j][0], -Gx);
                atomicAdd(&g_G[j][1], -Gy);
                atomicAdd(&g_G[j][2], -Gz);
                float H[6];
                H[0] = 8.f * (pk * Kxx + p3 * Rxx);
                H[1] = 8.f * (pk * Kyy + p3 * Ryy);
                H[2] = 8.f * (pk * Kzz + p3 * Rzz);
                H[3] = 8.f * (pk * Kxy + p3 * Rxy);
                H[4] = 8.f * (pk * Kxz + p3 * Rxz);
                H[5] = 8.f * (pk * Kyz + p3 * Ryz);
                int fmi = sfm[i], fmj = sfm[j];
                #pragma unroll
                for (int c = 0; c < 6; c++) {
                    atomicAdd(&g_U[i][c], H[c]);
                    atomicAdd(&g_U[j][c], H[c]);
                }
                if (fmj >= 0)
                    #pragma unroll
                    for (int c = 0; c < 6; c++) atomicAdd(&g_T[i * NMOL + fmj][c], H[c]);
                if (fmi >= 0)
                    #pragma unroll
                    for (int c = 0; c < 6; c++) atomicAdd(&g_T[j * NMOL + fmi][c], H[c]);
            }
        }
        float se = blockReduce256(E, red);
        if (t == 0) atomicAdd(&g_Ec, (double)se);
    } else {
        // ---- born pairs ----
        int p = (blockIdx.x - NBLK_PAIR) * 256 + t;
        __shared__ float sE[NMOL];
        if (t < NMOL) sE[t] = 0.f;
        __syncthreads();

        int i = ii[p], j = jj[p];
        float rx = sRx[j] - sRx[i] + off[p * 3 + 0];
        float ry = sRy[j] - sRy[i] + off[p * 3 + 1];
        float rz = sRz[j] - sRz[i] + off[p * 3 + 2];
        float d2 = rx * rx + ry * ry + rz * rz;
        float d  = sqrtf(d2);

        if (d < 6.0f) {
            float n  = n_[p], r0 = r0_[p];
            float qq = fabsf(sq[i] * sq[j]);
            float B  = qq * __powf(r0, n - 1.f) * __fdividef(1.f, n);
            float dn = __powf(d, -n);
            float cn = __powf(6.0f, -n);
            float y  = B * (dn - cn);
            atomicAdd(&sE[idxm[i]], 0.5f * KEC * y);
            float f     = 0.5f * KEC;
            float invd  = __fdividef(1.f, d);
            float invd2 = invd * invd;
            float yp  = -n * B * dn * invd;
            float ypp = n * (n + 1.f) * B * dn * invd2;
            float s1  = f * yp * invd;
            atomicAdd(&g_G[j][0],  s1 * rx);
            atomicAdd(&g_G[j][1],  s1 * ry);
            atomicAdd(&g_G[j][2],  s1 * rz);
            atomicAdd(&g_G[i][0], -s1 * rx);
            atomicAdd(&g_G[i][1], -s1 * ry);
            atomicAdd(&g_G[i][2], -s1 * rz);
            float w = (f * ypp - s1) * invd2;
            float H[6];
            H[0] = w * rx * rx + s1; H[1] = w * ry * ry + s1; H[2] = w * rz * rz + s1;
            H[3] = w * rx * ry; H[4] = w * rx * rz; H[5] = w * ry * rz;
            int fmi = sfm[i], fmj = sfm[j];
            #pragma unroll
            for (int c = 0; c < 6; c++) {
                atomicAdd(&g_U[i][c], H[c]);
                atomicAdd(&g_U[j][c], H[c]);
            }
            if (fmj >= 0)
                #pragma unroll
                for (int c = 0; c < 6; c++) atomicAdd(&g_T[i * NMOL + fmj][c], H[c]);
            if (fmi >= 0)
                #pragma unroll
                for (int c = 0; c < 6; c++) atomicAdd(&g_T[j * NMOL + fmi][c], H[c]);
        }
        __syncthreads();
        if (t < NMOL) atomicAdd(&g_Eb[t], (double)sE[t]);
    }
}

__global__ void k_fin(const float* __restrict__ q, const int* __restrict__ idx_m,
                      const int* __restrict__ is_film, float* __restrict__ out) {
    int a = threadIdx.x;
    __shared__ float sff[NMOL * 3];
    __shared__ float sfn[NMOL * 3];
    __shared__ float red[32];
    if (a < NMOL * 3) { sff[a] = 0.f; sfn[a] = 0.f; }
    __syncthreads();

    float Gx = g_G[a][0], Gy = g_G[a][1], Gz = g_G[a][2];
    int m = idx_m[a];
    bool film = (is_film[a] > 0);
    if (film) {
        atomicAdd(&sff[m * 3 + 0], -Gx);
        atomicAdd(&sff[m * 3 + 1], -Gy);
        atomicAdd(&sff[m * 3 + 2], -Gz);
    }
    float qa = q[a];
    float sq2 = blockReduce256(qa * qa, red);  // syncthreads inside makes sff visible

    // HVP: Hv_a = U_a * v_a - Sum_m T_am * ff_m, v_a = film_a * ff_{m(a)}
    float vx = film ? sff[m * 3 + 0] : 0.f;
    float vy = film ? sff[m * 3 + 1] : 0.f;
    float vz = film ? sff[m * 3 + 2] : 0.f;
    float U0 = g_U[a][0], U1 = g_U[a][1], U2 = g_U[a][2];
    float U3 = g_U[a][3], U4 = g_U[a][4], U5 = g_U[a][5];
    float Hvx = U0 * vx + U3 * vy + U4 * vz;
    float Hvy = U3 * vx + U1 * vy + U5 * vz;
    float Hvz = U4 * vx + U5 * vy + U2 * vz;
    #pragma unroll
    for (int m2 = 0; m2 < NMOL; m2++) {
        float* Tp = g_T[a * NMOL + m2];
        float fx = sff[m2 * 3 + 0], fy = sff[m2 * 3 + 1], fz = sff[m2 * 3 + 2];
        Hvx -= Tp[0] * fx + Tp[3] * fy + Tp[4] * fz;
        Hvy -= Tp[3] * fx + Tp[1] * fy + Tp[5] * fz;
        Hvz -= Tp[4] * fx + Tp[5] * fy + Tp[2] * fz;
    }
    if (film) {
        atomicAdd(&sfn[m * 3 + 0], Hvx);
        atomicAdd(&sfn[m * 3 + 1], Hvy);
        atomicAdd(&sfn[m * 3 + 2], Hvz);
    }
    __syncthreads();

    if (a == 0) {
        float self = -(AA / SQRTPI_F) * KEC * sq2;
        float yc = (float)g_Ec + self;
        out[4] = yc;
        #pragma unroll
        for (int m2 = 0; m2 < NMOL; m2++) {
            float yb = (float)g_Eb[m2];
            out[m2]     = yc + yb;
            out[5 + m2] = yb;
            float fx = sff[m2 * 3 + 0], fy = sff[m2 * 3 + 1], fz = sff[m2 * 3 + 2];
            out[9 + m2] = fx * fx + fy * fy + fz * fz;
        }
        g_Ec = 0.0;
    }
    if (a < NMOL * 3) out[13 + a] = -2.f * sfn[a];
    if (a < NMOL) g_Eb[a] = 0.0;

    // re-zero accumulators this thread owns (for the next graph replay)
    g_G[a][0] = 0.f; g_G[a][1] = 0.f; g_G[a][2] = 0.f;
    #pragma unroll
    for (int c = 0; c < 6; c++) g_U[a][c] = 0.f;
    #pragma unroll
    for (int m2 = 0; m2 < NMOL; m2++)
        #pragma unroll
        for (int c = 0; c < 6; c++) g_T[a * NMOL + m2][c] = 0.f;
}

extern "C" void kernel_launch(void* const* d_in, const int* in_sizes, int n_in,
                              void* d_out, int out_size) {
    const float* R      = (const float*)d_in[0];
    const float* shift  = (const float*)d_in[1];
    const float* q      = (const float*)d_in[2];
    const float* off    = (const float*)d_in[3];
    const float* cell   = (const float*)d_in[4];
    const float* recip  = (const float*)d_in[5];
    const float* r0_ij  = (const float*)d_in[6];
    const float* n_ij   = (const float*)d_in[7];
    const int*   idx_i  = (const int*)d_in[8];
    const int*   idx_j  = (const int*)d_in[9];
    const int*   idx_m  = (const int*)d_in[10];
    const int*   isf    = (const int*)d_in[11];
    float* out = (float*)d_out;

    k_main<<<NBLK_PAIR + NPAIRS / 256, 256>>>(R, shift, q, cell, recip, off,
                                              r0_ij, n_ij, idx_i, idx_j, idx_m, isf);
    k_fin<<<1, 256>>>(q, idx_m, isf, out);
}